// round 13
// baseline (speedup 1.0000x reference)
#include <cuda_runtime.h>
#include <cuda_fp16.h>
#include <math_constants.h>
#include <cstdint>

#define N_NODES 8192
#define DEG     16
#define NBR     (DEG + 1)
#define F_IN    1024
#define F_OUT   128
#define H_HEADS 8
#define J_DIM   (H_HEADS * F_OUT)   // 1024
#define BK      32
#define NCHUNK  (F_IN / BK)         // 32

#define BM      64                   // rows per tile
#define TILES   (H_HEADS * (N_NODES / BM))   // 1024
#define GRID_P  296                  // persistent CTAs (2 per SM)

#define ROW_HF   40                  // fp16 per smem row (80 B, conflict-free)
#define A_HALVES (BM * ROW_HF)       // 2560
#define B_HALVES (F_OUT * ROW_HF)    // 5120
#define BUF_HALVES (A_HALVES + B_HALVES)   // 7680
#define HS_STRIDE 132                // epilogue staging row stride (floats)

// Scratch (allocation-free rule: __device__ globals)
__device__ __half g_hh[N_NODES * J_DIM];               // 16 MB projected features (fp16)
__device__ __half g_Ahi[N_NODES * F_IN];               // 16 MB
__device__ __half g_Whi[H_HEADS * F_OUT * F_IN];       // 2 MB  [h][o][k]
__device__ float g_sdst[H_HEADS * N_NODES];
__device__ float g_ssrc[H_HEADS * N_NODES];

// ---------------------------------------------------------------------------
static __device__ __forceinline__ uint32_t smem_u32(const void* p) {
    uint32_t a;
    asm("{ .reg .u64 t; cvta.to.shared.u64 t, %1; cvt.u32.u64 %0, t; }" : "=r"(a) : "l"(p));
    return a;
}
#define CP_ASYNC16(dst_u32, src_ptr) \
    asm volatile("cp.async.cg.shared.global [%0], [%1], 16;" :: "r"(dst_u32), "l"(src_ptr))
#define CP_COMMIT() asm volatile("cp.async.commit_group;" ::: "memory")
#define CP_WAIT(n)  asm volatile("cp.async.wait_group %0;" :: "n"(n) : "memory")

static __device__ __forceinline__ void mma_fp16(float* c, const uint32_t* a, const uint32_t* b) {
    asm volatile(
        "mma.sync.aligned.m16n8k16.row.col.f32.f16.f16.f32 "
        "{%0,%1,%2,%3}, {%4,%5,%6,%7}, {%8,%9}, {%0,%1,%2,%3};"
        : "+f"(c[0]), "+f"(c[1]), "+f"(c[2]), "+f"(c[3])
        : "r"(a[0]), "r"(a[1]), "r"(a[2]), "r"(a[3]), "r"(b[0]), "r"(b[1]));
}

// ---------------------------------------------------------------------------
// Kernel 0a: cast features to fp16 (same [n][k] layout)
// ---------------------------------------------------------------------------
__global__ void castA(const float* __restrict__ A) {
    int idx = (blockIdx.x * blockDim.x + threadIdx.x) * 4;   // 4 floats per thread
    float4 v = *(const float4*)(A + idx);
    __half2* ph = (__half2*)(g_Ahi + idx);
    ph[0] = __floats2half2_rn(v.x, v.y);
    ph[1] = __floats2half2_rn(v.z, v.w);
}

// ---------------------------------------------------------------------------
// Kernel 0b: W[h][k][o] -> Whi[h][o][k]  (transpose + fp16 round)
// ---------------------------------------------------------------------------
__global__ void castW(const float* __restrict__ W) {
    __shared__ float t[32][33];
    int h = blockIdx.z, o0 = blockIdx.x * 32, k0 = blockIdx.y * 32;
    const float* Wp = W + (size_t)h * F_IN * F_OUT;
    size_t tbase = (size_t)h * F_OUT * F_IN;
    int tx = threadIdx.x, ty = threadIdx.y;
    #pragma unroll
    for (int r = 0; r < 32; r += 8)
        t[ty + r][tx] = Wp[(size_t)(k0 + ty + r) * F_OUT + o0 + tx];
    __syncthreads();
    #pragma unroll
    for (int r = 0; r < 32; r += 8) {
        float v = t[tx][ty + r];
        g_Whi[tbase + (size_t)(o0 + ty + r) * F_IN + k0 + tx] = __float2half_rn(v);
    }
}

// ---------------------------------------------------------------------------
// Kernel 1: persistent single-pass fp16 GEMM. 1024 tiles of 64x128(one head),
// 296 CTAs x (3..4) tiles, occ=2/SM so epilogue bubbles overlap across CTAs.
// Epilogue per tile: bias, fused score dots, fp16 g_hh store.
// ---------------------------------------------------------------------------
__global__ __launch_bounds__(256, 2)
void gemm_tc(const float* __restrict__ bW,     // [H, F_OUT]
             const float* __restrict__ a_att)  // [H, 2*F_OUT]
{
    extern __shared__ float4 dsm4[];
    __half* sb = (__half*)dsm4;
    __half* Sa[2] = { sb,            sb + BUF_HALVES };
    __half* Sb[2] = { sb + A_HALVES, sb + BUF_HALVES + A_HALVES };

    const int tid  = threadIdx.x;
    const int wid  = tid >> 5;
    const int lane = tid & 31;
    const int warp_m = wid >> 2;          // 0..1  (32 rows each)
    const int warp_n = wid & 3;           // 0..3  (32 cols each)
    const int gid = lane >> 2;            // 0..7
    const int tig = lane & 3;             // 0..3

    // loader slots: A = 256 x 16B (1/thread), B = 512 x 16B (2/thread)
    const int a_row = tid >> 2;           // 0..63
    const int a_col = (tid & 3) * 8;      // fp16 col 0,8,16,24
    int b_row[2], b_col[2];
    #pragma unroll
    for (int j = 0; j < 2; j++) {
        int idx = tid + j * 256;
        b_row[j] = idx >> 2;              // 0..127
        b_col[j] = (idx & 3) * 8;
    }

    for (int t = blockIdx.x; t < TILES; t += GRID_P) {
        const int head = t & 7;
        const int m0   = (t >> 3) * BM;
        const __half* Ah = g_Ahi + (size_t)m0 * F_IN;
        const __half* Bh = g_Whi + (size_t)head * F_OUT * F_IN;

        auto issue_chunk = [&](int chunk) {
            int k0 = chunk * BK;
            int buf = chunk & 1;
            uint32_t sa_u = smem_u32(Sa[buf]);
            uint32_t sbu  = smem_u32(Sb[buf]);
            CP_ASYNC16(sa_u + (uint32_t)(a_row * ROW_HF + a_col) * 2,
                       Ah + (size_t)a_row * F_IN + k0 + a_col);
            #pragma unroll
            for (int j = 0; j < 2; j++)
                CP_ASYNC16(sbu + (uint32_t)(b_row[j] * ROW_HF + b_col[j]) * 2,
                           Bh + (size_t)b_row[j] * F_IN + k0 + b_col[j]);
            CP_COMMIT();
        };

        float acc[2][4][4];
        #pragma unroll
        for (int i = 0; i < 2; i++)
            #pragma unroll
            for (int j = 0; j < 4; j++)
                #pragma unroll
                for (int r = 0; r < 4; r++) acc[i][j][r] = 0.f;

        issue_chunk(0);
        issue_chunk(1);

        for (int i = 0; i < NCHUNK; i++) {
            if (i < NCHUNK - 1) { CP_WAIT(1); } else { CP_WAIT(0); }
            __syncthreads();
            const int buf = i & 1;
            const uint32_t* ah = (const uint32_t*)Sa[buf];
            const uint32_t* bh = (const uint32_t*)Sb[buf];

            #pragma unroll
            for (int ks = 0; ks < 2; ks++) {          // K=16 per mma
                const int kw = ks * 8;                // word offset (fp16 pairs)

                uint32_t bfh[4][2];
                #pragma unroll
                for (int nt = 0; nt < 4; nt++) {
                    int n = warp_n * 32 + nt * 8 + gid;
                    int w0 = n * (ROW_HF / 2) + kw + tig;
                    bfh[nt][0] = bh[w0];     bfh[nt][1] = bh[w0 + 4];
                }
                uint32_t afh[2][4];
                #pragma unroll
                for (int mt = 0; mt < 2; mt++) {
                    int row = warp_m * 32 + mt * 16 + gid;
                    int w0 = row * (ROW_HF / 2) + kw + tig;
                    int w1 = (row + 8) * (ROW_HF / 2) + kw + tig;
                    afh[mt][0] = ah[w0]; afh[mt][1] = ah[w1];
                    afh[mt][2] = ah[w0 + 4]; afh[mt][3] = ah[w1 + 4];
                }

                #pragma unroll
                for (int mt = 0; mt < 2; mt++)
                    #pragma unroll
                    for (int nt = 0; nt < 4; nt++)
                        mma_fp16(acc[mt][nt], afh[mt], bfh[nt]);
            }
            __syncthreads();
            if (i + 2 < NCHUNK) issue_chunk(i + 2);
        }

        // ---- epilogue: stage (acc+bias) in smem, dots + fp16 g_hh stores ----
        float* hs = (float*)dsm4;   // 64 x HS_STRIDE floats = 33792 B
        const float* bias = bW + head * F_OUT;
        #pragma unroll
        for (int mt = 0; mt < 2; mt++) {
            #pragma unroll
            for (int nt = 0; nt < 4; nt++) {
                int row = warp_m * 32 + mt * 16 + gid;
                int col = warp_n * 32 + nt * 8 + 2 * tig;
                float b0 = bias[col], b1 = bias[col + 1];
                float2 v0 = make_float2(acc[mt][nt][0] + b0, acc[mt][nt][1] + b1);
                float2 v1 = make_float2(acc[mt][nt][2] + b0, acc[mt][nt][3] + b1);
                *(float2*)&hs[(size_t)row * HS_STRIDE + col]       = v0;
                *(float2*)&hs[(size_t)(row + 8) * HS_STRIDE + col] = v1;
            }
        }
        __syncthreads();

        // score dots: warp w owns rows w*8 .. w*8+7
        const float* ad = a_att + head * 2 * F_OUT;
        const float* as = ad + F_OUT;
        #pragma unroll
        for (int it = 0; it < 8; it++) {
            int row = wid * 8 + it;
            float pd = 0.f, ps = 0.f;
            #pragma unroll
            for (int j = 0; j < 4; j++) {
                int c = lane + 32 * j;
                float v = hs[(size_t)row * HS_STRIDE + c];
                pd = fmaf(v, ad[c], pd);
                ps = fmaf(v, as[c], ps);
            }
            #pragma unroll
            for (int off = 16; off > 0; off >>= 1) {
                pd += __shfl_xor_sync(0xFFFFFFFFu, pd, off);
                ps += __shfl_xor_sync(0xFFFFFFFFu, ps, off);
            }
            if (lane == 0) {
                g_sdst[head * N_NODES + m0 + row] = pd;
                g_ssrc[head * N_NODES + m0 + row] = ps;
            }
        }

        // coalesced fp16 g_hh stores: 2048 x uint2
        #pragma unroll
        for (int it = 0; it < 8; it++) {
            int idx = tid + it * 256;
            int row = idx >> 5;
            int c4  = (idx & 31) * 4;
            float4 v = *(const float4*)&hs[(size_t)row * HS_STRIDE + c4];
            __half2 p0 = __floats2half2_rn(v.x, v.y);
            __half2 p1 = __floats2half2_rn(v.z, v.w);
            uint2 pk;
            pk.x = *(uint32_t*)&p0;
            pk.y = *(uint32_t*)&p1;
            *(uint2*)(g_hh + (size_t)(m0 + row) * J_DIM + head * F_OUT + c4) = pk;
        }
        __syncthreads();   // hs dead before next tile's buffers overwrite it
    }
}

// ---------------------------------------------------------------------------
// Kernel 2: softmax over 17 neighbors + weighted gather-aggregate (fp16 gather).
// One warp per (h,n).
// ---------------------------------------------------------------------------
__global__ void attn_kernel(const int* __restrict__ adj,
                            const float* __restrict__ ba,
                            float* __restrict__ out)
{
    int w = (blockIdx.x * blockDim.x + threadIdx.x) >> 5;
    int lane = threadIdx.x & 31;
    if (w >= H_HEADS * N_NODES) return;
    int h = w & (H_HEADS - 1);
    int n = w >> 3;

    int nbr = 0;
    float sc = -CUDART_INF_F;
    if (lane < NBR) {
        nbr = (lane < DEG) ? adj[n * DEG + lane] : n;
        float x = g_sdst[h * N_NODES + n] + g_ssrc[h * N_NODES + nbr] + ba[h];
        sc = (x > 0.f) ? x : 0.2f * x;
    }

    float m = sc;
    #pragma unroll
    for (int off = 16; off > 0; off >>= 1)
        m = fmaxf(m, __shfl_xor_sync(0xFFFFFFFFu, m, off));

    float e = (lane < NBR) ? __expf(sc - m) : 0.f;
    float s = e;
    #pragma unroll
    for (int off = 16; off > 0; off >>= 1)
        s += __shfl_xor_sync(0xFFFFFFFFu, s, off);

    float alpha = e / s;

    float4 acc = make_float4(0.f, 0.f, 0.f, 0.f);
    #pragma unroll
    for (int d = 0; d < NBR; d++) {
        int nb = __shfl_sync(0xFFFFFFFFu, nbr, d);
        float al = __shfl_sync(0xFFFFFFFFu, alpha, d);
        uint2 pk = *(const uint2*)(g_hh + (size_t)nb * J_DIM + h * F_OUT + lane * 4);
        __half2 p0 = *(__half2*)&pk.x;
        __half2 p1 = *(__half2*)&pk.y;
        float2 f0 = __half22float2(p0);
        float2 f1 = __half22float2(p1);
        acc.x = fmaf(al, f0.x, acc.x);
        acc.y = fmaf(al, f0.y, acc.y);
        acc.z = fmaf(al, f1.x, acc.z);
        acc.w = fmaf(al, f1.y, acc.w);
    }
    *(float4*)(out + (size_t)n * J_DIM + h * F_OUT + lane * 4) = acc;
}

// ---------------------------------------------------------------------------
extern "C" void kernel_launch(void* const* d_in, const int* in_sizes, int n_in,
                              void* d_out, int out_size)
{
    const float* features = (const float*)d_in[0];   // [8192, 1024]
    const int*   adj      = (const int*)  d_in[1];   // [8192, 16]
    const float* W        = (const float*)d_in[2];   // [8, 1024, 128]
    const float* bW       = (const float*)d_in[3];   // [8, 128]
    const float* a        = (const float*)d_in[4];   // [8, 256]
    const float* ba       = (const float*)d_in[5];   // [8]
    float* out = (float*)d_out;                      // [8192, 1024]

    // 0) cast features / W to fp16 (W also transposed to K-major)
    castA<<<(N_NODES * F_IN) / (256 * 4), 256>>>(features);
    castW<<<dim3(F_OUT / 32, F_IN / 32, H_HEADS), dim3(32, 8)>>>(W);

    // 1) persistent fp16 GEMM (+ fused bias & score dots)
    const int dsmem = 34816;   // >= max(buffers 30720, epilogue 33792)
    cudaFuncSetAttribute(gemm_tc, cudaFuncAttributeMaxDynamicSharedMemorySize, dsmem);
    gemm_tc<<<GRID_P, 256, dsmem>>>(bW, a);

    // 2) softmax + aggregate (fp16 gather)
    int warps = H_HEADS * N_NODES;
    attn_kernel<<<(warps * 32) / 256, 256>>>(adj, ba, out);
}

// round 14
// speedup vs baseline: 1.0108x; 1.0108x over previous
#include <cuda_runtime.h>
#include <cuda_fp16.h>
#include <math_constants.h>
#include <cstdint>

#define N_NODES 8192
#define DEG     16
#define NBR     (DEG + 1)
#define F_IN    1024
#define F_OUT   128
#define H_HEADS 8
#define J_DIM   (H_HEADS * F_OUT)   // 1024
#define BK      32
#define NCHUNK  (F_IN / BK)         // 32

#define BM      64                   // rows per tile
#define TILES   (H_HEADS * (N_NODES / BM))   // 1024
#define GRID_P  444                  // persistent CTAs (3 per SM)
#define NTHR    128                  // 4 warps per CTA

#define ROW_HF   40                  // fp16 per smem row (80 B, conflict-free)
#define A_HALVES (BM * ROW_HF)       // 2560
#define B_HALVES (F_OUT * ROW_HF)    // 5120
#define BUF_HALVES (A_HALVES + B_HALVES)   // 7680
#define HS_STRIDE 132                // epilogue staging row stride (floats)

// Scratch (allocation-free rule: __device__ globals)
__device__ __half g_hh[N_NODES * J_DIM];               // 16 MB projected features (fp16)
__device__ __half g_Ahi[N_NODES * F_IN];               // 16 MB
__device__ __half g_Whi[H_HEADS * F_OUT * F_IN];       // 2 MB  [h][o][k]
__device__ float g_sdst[H_HEADS * N_NODES];
__device__ float g_ssrc[H_HEADS * N_NODES];

// ---------------------------------------------------------------------------
static __device__ __forceinline__ uint32_t smem_u32(const void* p) {
    uint32_t a;
    asm("{ .reg .u64 t; cvta.to.shared.u64 t, %1; cvt.u32.u64 %0, t; }" : "=r"(a) : "l"(p));
    return a;
}
#define CP_ASYNC16(dst_u32, src_ptr) \
    asm volatile("cp.async.cg.shared.global [%0], [%1], 16;" :: "r"(dst_u32), "l"(src_ptr))
#define CP_COMMIT() asm volatile("cp.async.commit_group;" ::: "memory")
#define CP_WAIT(n)  asm volatile("cp.async.wait_group %0;" :: "n"(n) : "memory")

static __device__ __forceinline__ void mma_fp16(float* c, const uint32_t* a, const uint32_t* b) {
    asm volatile(
        "mma.sync.aligned.m16n8k16.row.col.f32.f16.f16.f32 "
        "{%0,%1,%2,%3}, {%4,%5,%6,%7}, {%8,%9}, {%0,%1,%2,%3};"
        : "+f"(c[0]), "+f"(c[1]), "+f"(c[2]), "+f"(c[3])
        : "r"(a[0]), "r"(a[1]), "r"(a[2]), "r"(a[3]), "r"(b[0]), "r"(b[1]));
}

// ---------------------------------------------------------------------------
// Kernel 0a: cast features to fp16 (same [n][k] layout)
// ---------------------------------------------------------------------------
__global__ void castA(const float* __restrict__ A) {
    int idx = (blockIdx.x * blockDim.x + threadIdx.x) * 4;   // 4 floats per thread
    float4 v = *(const float4*)(A + idx);
    __half2* ph = (__half2*)(g_Ahi + idx);
    ph[0] = __floats2half2_rn(v.x, v.y);
    ph[1] = __floats2half2_rn(v.z, v.w);
}

// ---------------------------------------------------------------------------
// Kernel 0b: W[h][k][o] -> Whi[h][o][k]  (transpose + fp16 round)
// ---------------------------------------------------------------------------
__global__ void castW(const float* __restrict__ W) {
    __shared__ float t[32][33];
    int h = blockIdx.z, o0 = blockIdx.x * 32, k0 = blockIdx.y * 32;
    const float* Wp = W + (size_t)h * F_IN * F_OUT;
    size_t tbase = (size_t)h * F_OUT * F_IN;
    int tx = threadIdx.x, ty = threadIdx.y;
    #pragma unroll
    for (int r = 0; r < 32; r += 8)
        t[ty + r][tx] = Wp[(size_t)(k0 + ty + r) * F_OUT + o0 + tx];
    __syncthreads();
    #pragma unroll
    for (int r = 0; r < 32; r += 8) {
        float v = t[tx][ty + r];
        g_Whi[tbase + (size_t)(o0 + ty + r) * F_IN + k0 + tx] = __float2half_rn(v);
    }
}

// ---------------------------------------------------------------------------
// Kernel 1: persistent single-pass fp16 GEMM. 1024 tiles of 64x128 (one head),
// 444 CTAs of 4 warps (occ=3/SM), warp tile 64x32 (same MMA density as the
// 131.6us kernel), per-SM tile quantum 7 vs 6.92 ideal.
// Epilogue per tile: bias, fused score dots, fp16 g_hh store.
// ---------------------------------------------------------------------------
__global__ __launch_bounds__(NTHR, 3)
void gemm_tc(const float* __restrict__ bW,     // [H, F_OUT]
             const float* __restrict__ a_att)  // [H, 2*F_OUT]
{
    extern __shared__ float4 dsm4[];
    __half* sb = (__half*)dsm4;
    __half* Sa[2] = { sb,            sb + BUF_HALVES };
    __half* Sb[2] = { sb + A_HALVES, sb + BUF_HALVES + A_HALVES };

    const int tid  = threadIdx.x;
    const int wid  = tid >> 5;            // 0..3 = warp_n (32 cols each)
    const int lane = tid & 31;
    const int gid = lane >> 2;            // 0..7
    const int tig = lane & 3;             // 0..3

    // loader slots: A = 256 x 16B (2/thread), B = 512 x 16B (4/thread)
    int a_row[2], a_col[2];
    #pragma unroll
    for (int j = 0; j < 2; j++) {
        int idx = tid + j * NTHR;
        a_row[j] = idx >> 2;              // 0..63
        a_col[j] = (idx & 3) * 8;         // fp16 col 0,8,16,24
    }
    int b_row[4], b_col[4];
    #pragma unroll
    for (int j = 0; j < 4; j++) {
        int idx = tid + j * NTHR;
        b_row[j] = idx >> 2;              // 0..127
        b_col[j] = (idx & 3) * 8;
    }

    for (int t = blockIdx.x; t < TILES; t += GRID_P) {
        const int head = t & 7;
        const int m0   = (t >> 3) * BM;
        const __half* Ah = g_Ahi + (size_t)m0 * F_IN;
        const __half* Bh = g_Whi + (size_t)head * F_OUT * F_IN;

        auto issue_chunk = [&](int chunk) {
            int k0 = chunk * BK;
            int buf = chunk & 1;
            uint32_t sa_u = smem_u32(Sa[buf]);
            uint32_t sbu  = smem_u32(Sb[buf]);
            #pragma unroll
            for (int j = 0; j < 2; j++)
                CP_ASYNC16(sa_u + (uint32_t)(a_row[j] * ROW_HF + a_col[j]) * 2,
                           Ah + (size_t)a_row[j] * F_IN + k0 + a_col[j]);
            #pragma unroll
            for (int j = 0; j < 4; j++)
                CP_ASYNC16(sbu + (uint32_t)(b_row[j] * ROW_HF + b_col[j]) * 2,
                           Bh + (size_t)b_row[j] * F_IN + k0 + b_col[j]);
            CP_COMMIT();
        };

        float acc[4][4][4];   // [mt 16-row][nt 8-col][frag]
        #pragma unroll
        for (int i = 0; i < 4; i++)
            #pragma unroll
            for (int j = 0; j < 4; j++)
                #pragma unroll
                for (int r = 0; r < 4; r++) acc[i][j][r] = 0.f;

        issue_chunk(0);
        issue_chunk(1);

        for (int i = 0; i < NCHUNK; i++) {
            if (i < NCHUNK - 1) { CP_WAIT(1); } else { CP_WAIT(0); }
            __syncthreads();
            const int buf = i & 1;
            const uint32_t* ah = (const uint32_t*)Sa[buf];
            const uint32_t* bh = (const uint32_t*)Sb[buf];

            #pragma unroll
            for (int ks = 0; ks < 2; ks++) {          // K=16 per mma
                const int kw = ks * 8;                // word offset (fp16 pairs)

                uint32_t bfh[4][2];
                #pragma unroll
                for (int nt = 0; nt < 4; nt++) {
                    int n = wid * 32 + nt * 8 + gid;
                    int w0 = n * (ROW_HF / 2) + kw + tig;
                    bfh[nt][0] = bh[w0];     bfh[nt][1] = bh[w0 + 4];
                }
                uint32_t afh[4][4];
                #pragma unroll
                for (int mt = 0; mt < 4; mt++) {
                    int row = mt * 16 + gid;
                    int w0 = row * (ROW_HF / 2) + kw + tig;
                    int w1 = (row + 8) * (ROW_HF / 2) + kw + tig;
                    afh[mt][0] = ah[w0]; afh[mt][1] = ah[w1];
                    afh[mt][2] = ah[w0 + 4]; afh[mt][3] = ah[w1 + 4];
                }

                #pragma unroll
                for (int mt = 0; mt < 4; mt++)
                    #pragma unroll
                    for (int nt = 0; nt < 4; nt++)
                        mma_fp16(acc[mt][nt], afh[mt], bfh[nt]);
            }
            __syncthreads();
            if (i + 2 < NCHUNK) issue_chunk(i + 2);
        }

        // ---- epilogue: stage (acc+bias) in smem, dots + fp16 g_hh stores ----
        float* hs = (float*)dsm4;   // 64 x HS_STRIDE floats = 33792 B
        const float* bias = bW + head * F_OUT;
        #pragma unroll
        for (int mt = 0; mt < 4; mt++) {
            #pragma unroll
            for (int nt = 0; nt < 4; nt++) {
                int row = mt * 16 + gid;
                int col = wid * 32 + nt * 8 + 2 * tig;
                float b0 = bias[col], b1 = bias[col + 1];
                float2 v0 = make_float2(acc[mt][nt][0] + b0, acc[mt][nt][1] + b1);
                float2 v1 = make_float2(acc[mt][nt][2] + b0, acc[mt][nt][3] + b1);
                *(float2*)&hs[(size_t)row * HS_STRIDE + col]       = v0;
                *(float2*)&hs[(size_t)(row + 8) * HS_STRIDE + col] = v1;
            }
        }
        __syncthreads();

        // score dots: warp w owns rows w*16 .. w*16+15
        const float* ad = a_att + head * 2 * F_OUT;
        const float* as = ad + F_OUT;
        #pragma unroll
        for (int it = 0; it < 16; it++) {
            int row = wid * 16 + it;
            float pd = 0.f, ps = 0.f;
            #pragma unroll
            for (int j = 0; j < 4; j++) {
                int c = lane + 32 * j;
                float v = hs[(size_t)row * HS_STRIDE + c];
                pd = fmaf(v, ad[c], pd);
                ps = fmaf(v, as[c], ps);
            }
            #pragma unroll
            for (int off = 16; off > 0; off >>= 1) {
                pd += __shfl_xor_sync(0xFFFFFFFFu, pd, off);
                ps += __shfl_xor_sync(0xFFFFFFFFu, ps, off);
            }
            if (lane == 0) {
                g_sdst[head * N_NODES + m0 + row] = pd;
                g_ssrc[head * N_NODES + m0 + row] = ps;
            }
        }

        // coalesced fp16 g_hh stores: 2048 x uint2 / 128 threads = 16 iters
        #pragma unroll
        for (int it = 0; it < 16; it++) {
            int idx = tid + it * NTHR;
            int row = idx >> 5;
            int c4  = (idx & 31) * 4;
            float4 v = *(const float4*)&hs[(size_t)row * HS_STRIDE + c4];
            __half2 p0 = __floats2half2_rn(v.x, v.y);
            __half2 p1 = __floats2half2_rn(v.z, v.w);
            uint2 pk;
            pk.x = *(uint32_t*)&p0;
            pk.y = *(uint32_t*)&p1;
            *(uint2*)(g_hh + (size_t)(m0 + row) * J_DIM + head * F_OUT + c4) = pk;
        }
        __syncthreads();   // hs dead before next tile's buffers overwrite it
    }
}

// ---------------------------------------------------------------------------
// Kernel 2: softmax over 17 neighbors + weighted gather-aggregate (fp16 gather).
// One warp per (h,n).
// ---------------------------------------------------------------------------
__global__ void attn_kernel(const int* __restrict__ adj,
                            const float* __restrict__ ba,
                            float* __restrict__ out)
{
    int w = (blockIdx.x * blockDim.x + threadIdx.x) >> 5;
    int lane = threadIdx.x & 31;
    if (w >= H_HEADS * N_NODES) return;
    int h = w & (H_HEADS - 1);
    int n = w >> 3;

    int nbr = 0;
    float sc = -CUDART_INF_F;
    if (lane < NBR) {
        nbr = (lane < DEG) ? adj[n * DEG + lane] : n;
        float x = g_sdst[h * N_NODES + n] + g_ssrc[h * N_NODES + nbr] + ba[h];
        sc = (x > 0.f) ? x : 0.2f * x;
    }

    float m = sc;
    #pragma unroll
    for (int off = 16; off > 0; off >>= 1)
        m = fmaxf(m, __shfl_xor_sync(0xFFFFFFFFu, m, off));

    float e = (lane < NBR) ? __expf(sc - m) : 0.f;
    float s = e;
    #pragma unroll
    for (int off = 16; off > 0; off >>= 1)
        s += __shfl_xor_sync(0xFFFFFFFFu, s, off);

    float alpha = e / s;

    float4 acc = make_float4(0.f, 0.f, 0.f, 0.f);
    #pragma unroll
    for (int d = 0; d < NBR; d++) {
        int nb = __shfl_sync(0xFFFFFFFFu, nbr, d);
        float al = __shfl_sync(0xFFFFFFFFu, alpha, d);
        uint2 pk = *(const uint2*)(g_hh + (size_t)nb * J_DIM + h * F_OUT + lane * 4);
        __half2 p0 = *(__half2*)&pk.x;
        __half2 p1 = *(__half2*)&pk.y;
        float2 f0 = __half22float2(p0);
        float2 f1 = __half22float2(p1);
        acc.x = fmaf(al, f0.x, acc.x);
        acc.y = fmaf(al, f0.y, acc.y);
        acc.z = fmaf(al, f1.x, acc.z);
        acc.w = fmaf(al, f1.y, acc.w);
    }
    *(float4*)(out + (size_t)n * J_DIM + h * F_OUT + lane * 4) = acc;
}

// ---------------------------------------------------------------------------
extern "C" void kernel_launch(void* const* d_in, const int* in_sizes, int n_in,
                              void* d_out, int out_size)
{
    const float* features = (const float*)d_in[0];   // [8192, 1024]
    const int*   adj      = (const int*)  d_in[1];   // [8192, 16]
    const float* W        = (const float*)d_in[2];   // [8, 1024, 128]
    const float* bW       = (const float*)d_in[3];   // [8, 128]
    const float* a        = (const float*)d_in[4];   // [8, 256]
    const float* ba       = (const float*)d_in[5];   // [8]
    float* out = (float*)d_out;                      // [8192, 1024]

    // 0) cast features / W to fp16 (W also transposed to K-major)
    castA<<<(N_NODES * F_IN) / (256 * 4), 256>>>(features);
    castW<<<dim3(F_OUT / 32, F_IN / 32, H_HEADS), dim3(32, 8)>>>(W);

    // 1) persistent fp16 GEMM (+ fused bias & score dots)
    const int dsmem = 34816;   // >= max(buffers 30720, epilogue 33792)
    cudaFuncSetAttribute(gemm_tc, cudaFuncAttributeMaxDynamicSharedMemorySize, dsmem);
    gemm_tc<<<GRID_P, NTHR, dsmem>>>(bW, a);

    // 2) softmax + aggregate (fp16 gather)
    int warps = H_HEADS * N_NODES;
    attn_kernel<<<(warps * 32) / 256, 256>>>(adj, ba, out);
}